// round 1
// baseline (speedup 1.0000x reference)
#include <cuda_runtime.h>
#include <math.h>

// Device globals for the precomputed bound (no cudaMalloc allowed).
__device__ float g_maxfd;
__device__ float g_lower;   // lower bound on s(x) for any x >= g_maxfd

static constexpr int NPARAM = 1024;  // I*O = 32*32

// One-block reduction over the 1024 (fd, sigma) params:
//   maxfd = max_ij fd_ij
//   C     = sum_ij sqrt((maxfd - fd_ij) / sigma_ij^2)
// Each term of s(x) is monotone increasing in x on x >= fd_ij, so for any
// x >= maxfd: s(x) >= C and every radicand is >= 0 (no NaN possible).
__global__ void fuzzy_prep_kernel(const float* __restrict__ fd,
                                  const float* __restrict__ sigma,
                                  int nparam) {
    __shared__ float sh[256];
    const int tid = threadIdx.x;

    // Pass 1: max(fd)
    float m = -INFINITY;
    for (int j = tid; j < nparam; j += 256) m = fmaxf(m, fd[j]);
    sh[tid] = m;
    __syncthreads();
    for (int s = 128; s > 0; s >>= 1) {
        if (tid < s) sh[tid] = fmaxf(sh[tid], sh[tid + s]);
        __syncthreads();
    }
    const float maxfd = sh[0];
    __syncthreads();

    // Pass 2: C = sum sqrt((maxfd - fd)/sigma^2)
    float acc = 0.0f;
    for (int j = tid; j < nparam; j += 256) {
        float sg = sigma[j];
        float d  = (maxfd - fd[j]) / (sg * sg);
        acc += sqrtf(d);
    }
    sh[tid] = acc;
    __syncthreads();
    for (int s = 128; s > 0; s >>= 1) {
        if (tid < s) sh[tid] += sh[tid + s];
        __syncthreads();
    }

    if (tid == 0) {
        g_maxfd = maxfd;
        g_lower = sh[0];   // NaN-safe: NaN >= threshold is false -> slow path
    }
}

// Honest per-element evaluation (fallback path).
__device__ __forceinline__ float fuzzy_eval(float x,
                                            const float* __restrict__ fd,
                                            const float* __restrict__ sigma,
                                            int nparam) {
    float s = 0.0f;
    for (int j = 0; j < nparam; j++) {
        float sg = sigma[j];
        float d  = (x - fd[j]) / (sg * sg);
        s += sqrtf(d);          // NaN if d < 0, propagates
    }
    float o = expf(-s);
    if (isnan(o)) o = x;        // reference's NaN fallback
    return o;
}

__global__ void fuzzy_main_kernel(const float4* __restrict__ x4,
                                  const float* __restrict__ fd,
                                  const float* __restrict__ sigma,
                                  float4* __restrict__ out4,
                                  int n4, int nparam) {
    const int i = blockIdx.x * blockDim.x + threadIdx.x;
    if (i >= n4) return;

    // exp(-s) is exactly 0.0f (through denormals) once s >= ~104.3;
    // 106 gives margin. If the bound doesn't hold, every lane falls back.
    const float maxfd = g_maxfd;
    const bool  fast_ok = (g_lower >= 106.0f);

    float4 xv = x4[i];
    float4 ov;
    float* xin  = reinterpret_cast<float*>(&xv);
    float* oout = reinterpret_cast<float*>(&ov);

#pragma unroll
    for (int k = 0; k < 4; k++) {
        float x = xin[k];
        float o;
        if (fast_ok && x >= maxfd) {
            o = 0.0f;   // s(x) >= g_lower >= 106 -> expf underflows to exact 0
        } else {
            o = fuzzy_eval(x, fd, sigma, nparam);
        }
        oout[k] = o;
    }
    out4[i] = ov;
}

// Scalar tail (only used if out_size % 4 != 0; not expected here).
__global__ void fuzzy_tail_kernel(const float* __restrict__ x,
                                  const float* __restrict__ fd,
                                  const float* __restrict__ sigma,
                                  float* __restrict__ out,
                                  int start, int n, int nparam) {
    const int i = start + blockIdx.x * blockDim.x + threadIdx.x;
    if (i >= n) return;
    const float maxfd = g_maxfd;
    const bool  fast_ok = (g_lower >= 106.0f);
    float xv = x[i];
    out[i] = (fast_ok && xv >= maxfd) ? 0.0f : fuzzy_eval(xv, fd, sigma, nparam);
}

extern "C" void kernel_launch(void* const* d_in, const int* in_sizes, int n_in,
                              void* d_out, int out_size) {
    const float* x     = (const float*)d_in[0];
    const float* fd    = (const float*)d_in[1];
    const float* sigma = (const float*)d_in[2];
    float* out = (float*)d_out;

    const int n      = out_size;        // B samples
    const int nparam = in_sizes[1];     // I*O

    fuzzy_prep_kernel<<<1, 256>>>(fd, sigma, nparam);

    const int n4 = n / 4;
    if (n4 > 0) {
        const int threads = 256;
        const int blocks  = (n4 + threads - 1) / threads;
        fuzzy_main_kernel<<<blocks, threads>>>(
            (const float4*)x, fd, sigma, (float4*)out, n4, nparam);
    }
    const int tail_start = n4 * 4;
    const int tail_n = n - tail_start;
    if (tail_n > 0) {
        fuzzy_tail_kernel<<<(tail_n + 255) / 256, 256>>>(
            x, fd, sigma, out, tail_start, n, nparam);
    }
}

// round 2
// speedup vs baseline: 1.3140x; 1.3140x over previous
#include <cuda_runtime.h>
#include <math.h>

// Honest per-element evaluation (fallback path, used only if the
// zero-bound doesn't hold for a given element / parameter set).
__device__ __forceinline__ float fuzzy_eval(float x,
                                            const float* __restrict__ fd,
                                            const float* __restrict__ sigma,
                                            int nparam) {
    float s = 0.0f;
    for (int j = 0; j < nparam; j++) {
        float sg = sigma[j];
        float d  = (x - fd[j]) / (sg * sg);
        s += sqrtf(d);          // NaN if d < 0, propagates
    }
    float o = expf(-s);
    if (isnan(o)) o = x;        // reference's NaN fallback
    return o;
}

// Fused kernel: each block recomputes the bound from the (tiny, L2-resident)
// parameter arrays, then applies the fast path to its float4 chunk.
//
// Bound: maxfd = max_ij fd_ij; C = sum_ij sqrt((maxfd - fd_ij)/sigma_ij^2).
// Each term of s(x) is monotone increasing in x for x >= fd_ij, so for any
// x >= maxfd: s(x) >= C with every radicand >= 0 (no NaN possible).
// expf(-s) underflows to exactly 0.0f once s >= ~104.3; threshold 106 for margin.
__global__ void __launch_bounds__(256)
fuzzy_fused_kernel(const float4* __restrict__ x4,
                   const float* __restrict__ fd,
                   const float* __restrict__ sigma,
                   float4* __restrict__ out4,
                   int n4, int nparam) {
    const int tid  = threadIdx.x;
    const int lane = tid & 31;
    const int wid  = tid >> 5;
    const int gid  = blockIdx.x * 256 + tid;

    // Issue the x load FIRST so its DRAM latency overlaps the bound reduction.
    float4 xv = make_float4(0.f, 0.f, 0.f, 0.f);
    const bool valid = (gid < n4);
    if (valid) xv = x4[gid];

    __shared__ float sred[8];
    __shared__ float s_maxfd, s_lower;

    // ---- Pass 1: maxfd ----
    float m = -INFINITY;
    for (int j = tid; j < nparam; j += 256) m = fmaxf(m, fd[j]);
#pragma unroll
    for (int o = 16; o > 0; o >>= 1) m = fmaxf(m, __shfl_xor_sync(0xffffffffu, m, o));
    if (lane == 0) sred[wid] = m;
    __syncthreads();
    if (tid < 32) {
        float mm = (lane < 8) ? sred[lane] : -INFINITY;
#pragma unroll
        for (int o = 4; o > 0; o >>= 1) mm = fmaxf(mm, __shfl_xor_sync(0xffffffffu, mm, o));
        if (lane == 0) s_maxfd = mm;
    }
    __syncthreads();
    const float maxfd = s_maxfd;

    // ---- Pass 2: C = sum sqrt((maxfd - fd)/sigma^2) ----
    float acc = 0.0f;
    for (int j = tid; j < nparam; j += 256) {
        float sg = sigma[j];
        float d  = (maxfd - fd[j]) / (sg * sg);   // fd now L1-hit
        acc += sqrtf(d);
    }
#pragma unroll
    for (int o = 16; o > 0; o >>= 1) acc += __shfl_xor_sync(0xffffffffu, acc, o);
    if (lane == 0) sred[wid] = acc;
    __syncthreads();
    if (tid < 32) {
        float ss = (lane < 8) ? sred[lane] : 0.0f;
#pragma unroll
        for (int o = 4; o > 0; o >>= 1) ss += __shfl_xor_sync(0xffffffffu, ss, o);
        if (lane == 0) s_lower = ss;
    }
    __syncthreads();
    // NaN-safe: NaN >= 106 is false -> slow path
    const bool fast_ok = (s_lower >= 106.0f);

    // ---- Apply ----
    if (!valid) return;

    float4 ov;
    float* xin  = reinterpret_cast<float*>(&xv);
    float* oout = reinterpret_cast<float*>(&ov);
#pragma unroll
    for (int k = 0; k < 4; k++) {
        float x = xin[k];
        float o;
        if (fast_ok && x >= maxfd) {
            o = 0.0f;   // s(x) >= C >= 106 -> expf underflows to exact 0
        } else {
            o = fuzzy_eval(x, fd, sigma, nparam);
        }
        oout[k] = o;
    }
    out4[gid] = ov;
}

// Scalar tail kernel (only if out_size % 4 != 0; not expected for B=262144).
__global__ void fuzzy_tail_kernel(const float* __restrict__ x,
                                  const float* __restrict__ fd,
                                  const float* __restrict__ sigma,
                                  float* __restrict__ out,
                                  int start, int n, int nparam) {
    const int i = start + blockIdx.x * blockDim.x + threadIdx.x;
    if (i >= n) return;
    // Recompute the bound serially (tail is tiny / normally never launched).
    float maxfd = -INFINITY;
    for (int j = 0; j < nparam; j++) maxfd = fmaxf(maxfd, fd[j]);
    float C = 0.0f;
    for (int j = 0; j < nparam; j++) {
        float sg = sigma[j];
        C += sqrtf((maxfd - fd[j]) / (sg * sg));
    }
    float xv = x[i];
    out[i] = (C >= 106.0f && xv >= maxfd) ? 0.0f : fuzzy_eval(xv, fd, sigma, nparam);
}

extern "C" void kernel_launch(void* const* d_in, const int* in_sizes, int n_in,
                              void* d_out, int out_size) {
    const float* x     = (const float*)d_in[0];
    const float* fd    = (const float*)d_in[1];
    const float* sigma = (const float*)d_in[2];
    float* out = (float*)d_out;

    const int n      = out_size;        // B samples
    const int nparam = in_sizes[1];     // I*O

    const int n4 = n / 4;
    if (n4 > 0) {
        const int blocks = (n4 + 255) / 256;
        fuzzy_fused_kernel<<<blocks, 256>>>(
            (const float4*)x, fd, sigma, (float4*)out, n4, nparam);
    }
    const int tail_start = n4 * 4;
    const int tail_n = n - tail_start;
    if (tail_n > 0) {
        fuzzy_tail_kernel<<<(tail_n + 255) / 256, 256>>>(
            x, fd, sigma, out, tail_start, n, nparam);
    }
}